// round 15
// baseline (speedup 1.0000x reference)
#include <cuda_runtime.h>

#define BB 16
#define HH 1024
#define WW 1280

#define TX 128          // tile width (pixels)
#define TY 8            // tile height = warps per block
#define CAP 9216        // staged-tile capacity in floats (36 KB)

// Per-batch coefficients:
// [0..8]   M   (3x3, row-major)        : K R^T K^-1
// [9..11]  Wv  (3)                     : K R^T (-t)
// [12..14] M2 row 2 (3)                : row 2 of (K R) K^-1
// [15]     W2z                         : (K t)[2]
__device__ float g_coef[BB][16];

__global__ void precompute_kernel(const float* __restrict__ trans,
                                  const float* __restrict__ rot,
                                  const float* __restrict__ intr) {
    int b = threadIdx.x;
    if (b >= BB) return;

    float K[3][3];
    #pragma unroll
    for (int i = 0; i < 3; i++)
        #pragma unroll
        for (int j = 0; j < 3; j++)
            K[i][j] = intr[i * 3 + j];

    float a00 = K[1][1]*K[2][2] - K[1][2]*K[2][1];
    float a01 = K[0][2]*K[2][1] - K[0][1]*K[2][2];
    float a02 = K[0][1]*K[1][2] - K[0][2]*K[1][1];
    float a10 = K[1][2]*K[2][0] - K[1][0]*K[2][2];
    float a11 = K[0][0]*K[2][2] - K[0][2]*K[2][0];
    float a12 = K[0][2]*K[1][0] - K[0][0]*K[1][2];
    float a20 = K[1][0]*K[2][1] - K[1][1]*K[2][0];
    float a21 = K[0][1]*K[2][0] - K[0][0]*K[2][1];
    float a22 = K[0][0]*K[1][1] - K[0][1]*K[1][0];
    float det = K[0][0]*a00 + K[0][1]*a10 + K[0][2]*a20;
    float id  = 1.0f / det;
    float Ki[3][3] = {{a00*id, a01*id, a02*id},
                      {a10*id, a11*id, a12*id},
                      {a20*id, a21*id, a22*id}};

    float R[3][3];
    #pragma unroll
    for (int i = 0; i < 3; i++)
        #pragma unroll
        for (int j = 0; j < 3; j++)
            R[i][j] = rot[b * 9 + i * 3 + j];

    float t0 = trans[b * 3 + 0], t1 = trans[b * 3 + 1], t2 = trans[b * 3 + 2];

    // temp = K * R^T
    float T[3][3];
    #pragma unroll
    for (int i = 0; i < 3; i++)
        #pragma unroll
        for (int k = 0; k < 3; k++)
            T[i][k] = K[i][0]*R[k][0] + K[i][1]*R[k][1] + K[i][2]*R[k][2];

    float Wv[3];
    #pragma unroll
    for (int i = 0; i < 3; i++)
        Wv[i] = -(T[i][0]*t0 + T[i][1]*t1 + T[i][2]*t2);

    float M[3][3];
    #pragma unroll
    for (int i = 0; i < 3; i++)
        #pragma unroll
        for (int k = 0; k < 3; k++)
            M[i][k] = T[i][0]*Ki[0][k] + T[i][1]*Ki[1][k] + T[i][2]*Ki[2][k];

    float KR2[3];
    #pragma unroll
    for (int k = 0; k < 3; k++)
        KR2[k] = K[2][0]*R[0][k] + K[2][1]*R[1][k] + K[2][2]*R[2][k];
    float M2r[3];
    #pragma unroll
    for (int k = 0; k < 3; k++)
        M2r[k] = KR2[0]*Ki[0][k] + KR2[1]*Ki[1][k] + KR2[2]*Ki[2][k];

    float W2z = K[2][0]*t0 + K[2][1]*t1 + K[2][2]*t2;

    float* c = g_coef[b];
    c[0] = M[0][0]; c[1] = M[0][1]; c[2] = M[0][2];
    c[3] = M[1][0]; c[4] = M[1][1]; c[5] = M[1][2];
    c[6] = M[2][0]; c[7] = M[2][1]; c[8] = M[2][2];
    c[9] = Wv[0];   c[10] = Wv[1];  c[11] = Wv[2];
    c[12] = M2r[0]; c[13] = M2r[1]; c[14] = M2r[2];
    c[15] = W2z;
}

// Tile layout: block = 128(x) x 8(y); warp w takes row y0+w, thread t
// handles x0+lane+32*i. The block's d2 gather footprint is bounded
// analytically (Mobius in z -> extremes at z in {1,10}; homography in
// (u,v) -> extremes at tile corners), staged into smem once, and gathers
// become near-conflict-free LDS (lanes = same row, consecutive x).
// Per-pixel out-of-bbox fallback -> global LDG; whole-block fallback if
// bbox exceeds CAP.
__global__ void __launch_bounds__(256, 6)
depth_warp_kernel(const float* __restrict__ d1,
                  const float* __restrict__ d2,
                  float* __restrict__ out) {
    __shared__ float tile[CAP];

    const int lane = threadIdx.x & 31;
    const int wid  = threadIdx.x >> 5;

    const int bid = blockIdx.x;
    const int tx  = bid % (WW / TX);               // 10 tiles in x
    const int ty  = (bid / (WW / TX)) % (HH / TY); // 128 tiles in y
    const int b   = bid / ((WW / TX) * (HH / TY)); // batch

    const int x0 = tx * TX;
    const int y  = ty * TY + wid;

    const float* c = g_coef[b];
    const float m00 = c[0], m01 = c[1], m02 = c[2];
    const float m10 = c[3], m11 = c[4], m12 = c[5];
    const float m20 = c[6], m21 = c[7], m22 = c[8];
    const float wv0 = c[9], wv1 = c[10], wv2 = c[11];
    const float q20 = c[12], q21 = c[13], q22 = c[14];
    const float w2z = c[15];

    const float* d2b = d2 + b * (HH * WW);

    // ---- bbox of the block's gather footprint (exact bounds + 1px pad) ----
    // Evaluate projection at 4 tile corners x 2 depth extremes (z=1, z=10).
    float minu =  1e30f, maxu = -1e30f, minv = 1e30f, maxv = -1e30f;
    {
        const float cx[2] = {(float)x0, (float)(x0 + TX - 1)};
        const float cy[2] = {(float)(ty * TY), (float)(ty * TY + TY - 1)};
        const float cz[2] = {1.0f, 10.0f};
        #pragma unroll
        for (int iy = 0; iy < 2; iy++) {
            const float r0 = fmaf(m01, cy[iy], m02);
            const float r1 = fmaf(m11, cy[iy], m12);
            const float r2 = fmaf(m21, cy[iy], m22);
            #pragma unroll
            for (int ixc = 0; ixc < 2; ixc++) {
                #pragma unroll
                for (int iz = 0; iz < 2; iz++) {
                    const float z1 = cz[iz];
                    const float fu = cx[ixc];
                    const float z2 = fmaf(z1, fmaf(m20, fu, r2), wv2);
                    const float nu = fmaf(z1, fmaf(m00, fu, r0), wv0);
                    const float nv = fmaf(z1, fmaf(m10, fu, r1), wv1);
                    const float inv = __fdividef(1.0f, z2);
                    const float uu = nu * inv;
                    const float vv = nv * inv;
                    minu = fminf(minu, uu); maxu = fmaxf(maxu, uu);
                    minv = fminf(minv, vv); maxv = fmaxf(maxv, vv);
                }
            }
        }
    }
    // clamped integer bbox, padded 1px for fp safety
    const int bx0 = min(max(__float2int_rd(minu) - 1, 0), WW - 1);
    const int bx1 = min(max(__float2int_rd(maxu) + 2, 0), WW - 1);
    const int by0 = min(max(__float2int_rd(minv) - 1, 0), HH - 1);
    const int by1 = min(max(__float2int_rd(maxv) + 2, 0), HH - 1);
    const int bw = bx1 - bx0 + 1;
    const int bh = by1 - by0 + 1;
    const int stride = bw + ((bw & 1) ? 2 : 1);     // odd stride
    const bool use_smem = (bh * stride <= CAP);     // uniform across block

    // ---- stage footprint (warp per row, coalesced) ----
    if (use_smem) {
        for (int r = wid; r < bh; r += TY) {
            const float* src = d2b + (by0 + r) * WW + bx0;
            float* dst = tile + r * stride;
            for (int cc = lane; cc < bw; cc += 32)
                dst[cc] = __ldg(src + cc);
        }
    }
    __syncthreads();

    const float fv = (float)y;
    const float ry0 = fmaf(m01, fv, m02);
    const float ry1 = fmaf(m11, fv, m12);
    const float ry2 = fmaf(m21, fv, m22);

    const int base = b * (HH * WW) + y * WW + x0 + lane;

    #pragma unroll
    for (int i = 0; i < 4; i++) {
        const float z1 = __ldg(d1 + base + 32 * i);
        const float fu = (float)(x0 + lane + 32 * i);
        const float z2 = fmaf(z1, fmaf(m20, fu, ry2), wv2);
        const float nu = fmaf(z1, fmaf(m00, fu, ry0), wv0);
        const float nv = fmaf(z1, fmaf(m10, fu, ry1), wv1);
        const float inv = __fdividef(1.0f, z2);
        const float u2 = nu * inv;
        const float v2 = nv * inv;

        const int ix0 = __float2int_rd(u2);
        const int iy0 = __float2int_rd(v2);
        const int ix1c = min(max(ix0 + 1, 0), WW - 1);
        const int ix0c = min(max(ix0, 0), WW - 1);
        const int iy1c = min(max(iy0 + 1, 0), HH - 1);
        const int iy0c = min(max(iy0, 0), HH - 1);

        float Da, Db, Dc, Dd;
        const bool inb = use_smem &
                         (ix0c >= bx0) & (ix1c <= bx1) &
                         (iy0c >= by0) & (iy1c <= by1);
        if (inb) {
            const int s0 = (iy0c - by0) * stride + (ix0c - bx0);
            const int s1 = (iy1c - by0) * stride + (ix0c - bx0);
            const int dx = ix1c - ix0c;
            Da = tile[s0];
            Db = tile[s1];
            Dc = tile[s0 + dx];
            Dd = tile[s1 + dx];
        } else {
            const float* row0 = d2b + iy0c * WW;
            const float* row1 = d2b + iy1c * WW;
            Da = __ldg(row0 + ix0c);
            Db = __ldg(row1 + ix0c);
            Dc = __ldg(row0 + ix1c);
            Dd = __ldg(row1 + ix1c);
        }

        const float x0f = (float)ix0c, x1f = (float)ix1c;
        const float y0f = (float)iy0c, y1f = (float)iy1c;

        const float wa = (x1f - u2) * (y1f - v2);
        const float wb = (x1f - u2) * (v2 - y0f);
        const float wc = (u2 - x0f) * (y1f - v2);
        const float wd = (u2 - x0f) * (v2 - y0f);

        // d1_calc at each corner: w2z + d2 * (q20*ix + q21*iy + q22)
        const float rp0 = fmaf(q21, y0f, q22);
        const float rp1 = fmaf(q21, y1f, q22);
        const float px0 = q20 * x0f;
        const float px1 = q20 * x1f;

        const float Ia = fmaf(Da, px0 + rp0, w2z);
        const float Ib = fmaf(Db, px0 + rp1, w2z);
        const float Ic = fmaf(Dc, px1 + rp0, w2z);
        const float Id = fmaf(Dd, px1 + rp1, w2z);

        out[base + 32 * i] = wa * Ia + wb * Ib + wc * Ic + wd * Id;
    }
}

extern "C" void kernel_launch(void* const* d_in, const int* in_sizes, int n_in,
                              void* d_out, int out_size) {
    const float* d1   = (const float*)d_in[0];
    const float* d2   = (const float*)d_in[1];
    const float* tr   = (const float*)d_in[2];
    const float* rot  = (const float*)d_in[3];
    const float* intr = (const float*)d_in[4];
    float* out = (float*)d_out;

    precompute_kernel<<<1, BB>>>(tr, rot, intr);

    const int blocks = (WW / TX) * (HH / TY) * BB;     // 10*128*16 = 20480
    depth_warp_kernel<<<blocks, 256>>>(d1, d2, out);
}

// round 16
// speedup vs baseline: 1.2367x; 1.2367x over previous
#include <cuda_runtime.h>

#define BB 16
#define HH 1024
#define WW 1280

#define TX 128
#define TY 16            // rows per block = warps per block (512 threads)

// Single-kernel design: per-batch warp/projection coefficients are computed
// redundantly per thread (~45 FLOPs, exploiting the triangular intrinsic
// K = [[fx,0,cx],[0,fy,cy],[0,0,1]] so K^-1 is analytic). This removes the
// separate precompute launch and the per-thread coefficient loads.
//
// Tile layout (validated R12/R13): block = 128(x) x 16(y); warp w takes row
// y0+w, thread lane handles x0+lane+32*i, i=0..3. Vertically-adjacent rows
// gather nearly identical d2 lines -> high L1 hit rate.
// Software pipeline (validated R5): (A) project, (B) issue all 16 scalar
// gather LDGs (scalar = optimal for scattered lanes), (C) weights+combine.
// __launch_bounds__(512, 4): 32 regs, 2048 threads/SM = full occupancy.
__global__ void __launch_bounds__(512, 4)
depth_warp_kernel(const float* __restrict__ d1,
                  const float* __restrict__ d2,
                  const float* __restrict__ trans,
                  const float* __restrict__ rot,
                  const float* __restrict__ intr,
                  float* __restrict__ out) {
    const int lane = threadIdx.x & 31;
    const int wid  = threadIdx.x >> 5;

    const int bid = blockIdx.x;
    const int tx  = bid % (WW / TX);                // 10 tiles in x
    const int ty  = (bid / (WW / TX)) % (HH / TY);  // 64 tiles in y
    const int b   = bid / ((WW / TX) * (HH / TY));  // batch

    const int x0 = tx * TX;
    const int y  = ty * TY + wid;

    // ---- per-thread coefficient computation (~45 FLOPs, broadcast loads) ----
    const float fx = __ldg(intr + 0);
    const float cx = __ldg(intr + 2);
    const float fy = __ldg(intr + 4);
    const float cy = __ldg(intr + 5);
    const float a0 = __fdividef(1.0f, fx);
    const float a1 = __fdividef(1.0f, fy);

    const float* Rb = rot + b * 9;
    const float r00 = __ldg(Rb + 0), r01 = __ldg(Rb + 1), r02 = __ldg(Rb + 2);
    const float r10 = __ldg(Rb + 3), r11 = __ldg(Rb + 4), r12 = __ldg(Rb + 5);
    const float r20 = __ldg(Rb + 6), r21 = __ldg(Rb + 7), r22 = __ldg(Rb + 8);
    const float t0 = __ldg(trans + b * 3 + 0);
    const float t1 = __ldg(trans + b * 3 + 1);
    const float t2 = __ldg(trans + b * 3 + 2);

    // T = K * R^T : T[i][j] built from R rows (R^T col j = R row j)
    const float T00 = fmaf(fx, r00, cx * r02);
    const float T01 = fmaf(fx, r10, cx * r12);
    const float T02 = fmaf(fx, r20, cx * r22);
    const float T10 = fmaf(fy, r01, cy * r02);
    const float T11 = fmaf(fy, r11, cy * r12);
    const float T12 = fmaf(fy, r21, cy * r22);
    const float T20 = r02, T21 = r12, T22 = r22;

    // M = T * K^-1  (K^-1 = [[a0,0,-cx*a0],[0,a1,-cy*a1],[0,0,1]])
    const float m00 = T00 * a0;
    const float m01 = T01 * a1;
    const float m02 = T02 - fmaf(T00, cx * a0, T01 * (cy * a1));
    const float m10 = T10 * a0;
    const float m11 = T11 * a1;
    const float m12 = T12 - fmaf(T10, cx * a0, T11 * (cy * a1));
    const float m20 = T20 * a0;
    const float m21 = T21 * a1;
    const float m22 = T22 - fmaf(T20, cx * a0, T21 * (cy * a1));

    // Wv = T * (-t)
    const float wv0 = -fmaf(T00, t0, fmaf(T01, t1, T02 * t2));
    const float wv1 = -fmaf(T10, t0, fmaf(T11, t1, T12 * t2));
    const float wv2 = -fmaf(T20, t0, fmaf(T21, t1, T22 * t2));

    // M2 row 2 = (K R)[2][:] * K^-1 ; (K R) row 2 = R row 2
    const float q20 = r20 * a0;
    const float q21 = r21 * a1;
    const float q22 = r22 - fmaf(r20, cx * a0, r21 * (cy * a1));
    // W2z = (K t)[2] = t2
    const float w2z = t2;

    const float* d2b = d2 + b * (HH * WW);

    const float fv = (float)y;
    const float ry0 = fmaf(m01, fv, m02);
    const float ry1 = fmaf(m11, fv, m12);
    const float ry2 = fmaf(m21, fv, m22);

    const int base = b * (HH * WW) + y * WW + x0 + lane;

    // ---- phase A: project ----
    float u2a[4], v2a[4];
    #pragma unroll
    for (int i = 0; i < 4; i++) {
        const float z1 = __ldg(d1 + base + 32 * i);
        const float fu = (float)(x0 + lane + 32 * i);
        const float z2 = fmaf(z1, fmaf(m20, fu, ry2), wv2);
        const float nu = fmaf(z1, fmaf(m00, fu, ry0), wv0);
        const float nv = fmaf(z1, fmaf(m10, fu, ry1), wv1);
        const float inv = __fdividef(1.0f, z2);
        u2a[i] = nu * inv;
        v2a[i] = nv * inv;
    }

    // ---- phase B: issue all 16 gathers ----
    float Da[4], Db[4], Dc[4], Dd[4];
    #pragma unroll
    for (int i = 0; i < 4; i++) {
        const int ix0 = __float2int_rd(u2a[i]);
        const int iy0 = __float2int_rd(v2a[i]);
        const int ix1c = min(max(ix0 + 1, 0), WW - 1);
        const int ix0c = min(max(ix0, 0), WW - 1);
        const int iy1c = min(max(iy0 + 1, 0), HH - 1);
        const int iy0c = min(max(iy0, 0), HH - 1);
        const float* row0 = d2b + iy0c * WW;
        const float* row1 = d2b + iy1c * WW;
        Da[i] = __ldg(row0 + ix0c);
        Db[i] = __ldg(row1 + ix0c);
        Dc[i] = __ldg(row0 + ix1c);
        Dd[i] = __ldg(row1 + ix1c);
    }

    // ---- phase C: weights + combine + store ----
    #pragma unroll
    for (int i = 0; i < 4; i++) {
        const float u2 = u2a[i];
        const float v2 = v2a[i];
        const int ix0 = __float2int_rd(u2);
        const int iy0 = __float2int_rd(v2);
        const int ix1c = min(max(ix0 + 1, 0), WW - 1);
        const int ix0c = min(max(ix0, 0), WW - 1);
        const int iy1c = min(max(iy0 + 1, 0), HH - 1);
        const int iy0c = min(max(iy0, 0), HH - 1);

        const float x0f = (float)ix0c, x1f = (float)ix1c;
        const float y0f = (float)iy0c, y1f = (float)iy1c;

        const float wa = (x1f - u2) * (y1f - v2);
        const float wb = (x1f - u2) * (v2 - y0f);
        const float wc = (u2 - x0f) * (y1f - v2);
        const float wd = (u2 - x0f) * (v2 - y0f);

        // d1_calc at each corner: w2z + d2 * (q20*ix + q21*iy + q22)
        const float rp0 = fmaf(q21, y0f, q22);
        const float rp1 = fmaf(q21, y1f, q22);
        const float px0 = q20 * x0f;
        const float px1 = q20 * x1f;

        const float Ia = fmaf(Da[i], px0 + rp0, w2z);
        const float Ib = fmaf(Db[i], px0 + rp1, w2z);
        const float Ic = fmaf(Dc[i], px1 + rp0, w2z);
        const float Id = fmaf(Dd[i], px1 + rp1, w2z);

        out[base + 32 * i] = wa * Ia + wb * Ib + wc * Ic + wd * Id;
    }
}

extern "C" void kernel_launch(void* const* d_in, const int* in_sizes, int n_in,
                              void* d_out, int out_size) {
    const float* d1   = (const float*)d_in[0];
    const float* d2   = (const float*)d_in[1];
    const float* tr   = (const float*)d_in[2];
    const float* rot  = (const float*)d_in[3];
    const float* intr = (const float*)d_in[4];
    float* out = (float*)d_out;

    const int blocks = (WW / TX) * (HH / TY) * BB;     // 10*64*16 = 10240
    depth_warp_kernel<<<blocks, 512>>>(d1, d2, tr, rot, intr, out);
}

// round 17
// speedup vs baseline: 1.9969x; 1.6148x over previous
#include <cuda_runtime.h>

#define BB 16
#define HH 1024
#define WW 1280

#define TX 128
#define TY 8             // rows per block = warps per block (256 threads)

// Single-launch design: per-batch projection coefficients are computed once
// per block by thread 0 into shared memory (analytic K^-1: K is
// [[fx,0,cx],[0,fy,cy],[0,0,1]]), then broadcast to all threads. This keeps
// the per-thread register profile identical to the validated R13 kernel
// (32 regs, 8 blocks/SM) while eliminating the separate precompute launch.
//
// smem coef layout:
// [0..8]   M   (3x3, row-major)        : K R^T K^-1
// [9..11]  Wv  (3)                     : K R^T (-t)
// [12..14] M2 row 2 (3)                : row 2 of (K R) K^-1
// [15]     W2z                         : (K t)[2] = t2
//
// Tile layout (validated R12/R13): block = 128(x) x 8(y); warp w takes row
// y0+w, lane handles x0+lane+32*i, i=0..3. Vertically-adjacent rows gather
// nearly identical d2 lines -> high L1 hit rate.
// Software pipeline (validated R5): (A) project, (B) issue all 16 scalar
// gather LDGs (scalar = optimal for scattered lanes), (C) weights+combine.
__global__ void __launch_bounds__(256, 8)
depth_warp_kernel(const float* __restrict__ d1,
                  const float* __restrict__ d2,
                  const float* __restrict__ trans,
                  const float* __restrict__ rot,
                  const float* __restrict__ intr,
                  float* __restrict__ out) {
    __shared__ float cs[16];

    const int lane = threadIdx.x & 31;
    const int wid  = threadIdx.x >> 5;

    const int bid = blockIdx.x;
    const int tx  = bid % (WW / TX);                // 10 tiles in x
    const int ty  = (bid / (WW / TX)) % (HH / TY);  // 128 tiles in y
    const int b   = bid / ((WW / TX) * (HH / TY));  // batch

    if (threadIdx.x == 0) {
        const float fx = intr[0];
        const float cx = intr[2];
        const float fy = intr[4];
        const float cy = intr[5];
        const float a0 = __fdividef(1.0f, fx);
        const float a1 = __fdividef(1.0f, fy);

        const float* Rb = rot + b * 9;
        const float r00 = Rb[0], r01 = Rb[1], r02 = Rb[2];
        const float r10 = Rb[3], r11 = Rb[4], r12 = Rb[5];
        const float r20 = Rb[6], r21 = Rb[7], r22 = Rb[8];
        const float t0 = trans[b * 3 + 0];
        const float t1 = trans[b * 3 + 1];
        const float t2 = trans[b * 3 + 2];

        // T = K * R^T  (R^T column j = R row j)
        const float T00 = fmaf(fx, r00, cx * r02);
        const float T01 = fmaf(fx, r10, cx * r12);
        const float T02 = fmaf(fx, r20, cx * r22);
        const float T10 = fmaf(fy, r01, cy * r02);
        const float T11 = fmaf(fy, r11, cy * r12);
        const float T12 = fmaf(fy, r21, cy * r22);
        const float T20 = r02, T21 = r12, T22 = r22;

        const float ca = cx * a0;
        const float cb = cy * a1;

        // M = T * K^-1  (K^-1 = [[a0,0,-ca],[0,a1,-cb],[0,0,1]])
        cs[0] = T00 * a0;
        cs[1] = T01 * a1;
        cs[2] = T02 - fmaf(T00, ca, T01 * cb);
        cs[3] = T10 * a0;
        cs[4] = T11 * a1;
        cs[5] = T12 - fmaf(T10, ca, T11 * cb);
        cs[6] = T20 * a0;
        cs[7] = T21 * a1;
        cs[8] = T22 - fmaf(T20, ca, T21 * cb);
        // Wv = T * (-t)
        cs[9]  = -fmaf(T00, t0, fmaf(T01, t1, T02 * t2));
        cs[10] = -fmaf(T10, t0, fmaf(T11, t1, T12 * t2));
        cs[11] = -fmaf(T20, t0, fmaf(T21, t1, T22 * t2));
        // M2 row 2 = (K R)[2][:] * K^-1 ; (K R) row 2 = R row 2
        cs[12] = r20 * a0;
        cs[13] = r21 * a1;
        cs[14] = r22 - fmaf(r20, ca, r21 * cb);
        // W2z = (K t)[2] = t2
        cs[15] = t2;
    }
    __syncthreads();

    const float m00 = cs[0], m01 = cs[1], m02 = cs[2];
    const float m10 = cs[3], m11 = cs[4], m12 = cs[5];
    const float m20 = cs[6], m21 = cs[7], m22 = cs[8];
    const float wv0 = cs[9], wv1 = cs[10], wv2 = cs[11];
    const float q20 = cs[12], q21 = cs[13], q22 = cs[14];
    const float w2z = cs[15];

    const int x0 = tx * TX;
    const int y  = ty * TY + wid;

    const float* d2b = d2 + b * (HH * WW);

    const float fv = (float)y;
    const float ry0 = fmaf(m01, fv, m02);
    const float ry1 = fmaf(m11, fv, m12);
    const float ry2 = fmaf(m21, fv, m22);

    const int base = b * (HH * WW) + y * WW + x0 + lane;

    // ---- phase A: project ----
    float u2a[4], v2a[4];
    #pragma unroll
    for (int i = 0; i < 4; i++) {
        const float z1 = __ldg(d1 + base + 32 * i);
        const float fu = (float)(x0 + lane + 32 * i);
        const float z2 = fmaf(z1, fmaf(m20, fu, ry2), wv2);
        const float nu = fmaf(z1, fmaf(m00, fu, ry0), wv0);
        const float nv = fmaf(z1, fmaf(m10, fu, ry1), wv1);
        const float inv = __fdividef(1.0f, z2);
        u2a[i] = nu * inv;
        v2a[i] = nv * inv;
    }

    // ---- phase B: issue all 16 gathers ----
    float Da[4], Db[4], Dc[4], Dd[4];
    #pragma unroll
    for (int i = 0; i < 4; i++) {
        const int ix0 = __float2int_rd(u2a[i]);
        const int iy0 = __float2int_rd(v2a[i]);
        const int ix1c = min(max(ix0 + 1, 0), WW - 1);
        const int ix0c = min(max(ix0, 0), WW - 1);
        const int iy1c = min(max(iy0 + 1, 0), HH - 1);
        const int iy0c = min(max(iy0, 0), HH - 1);
        const float* row0 = d2b + iy0c * WW;
        const float* row1 = d2b + iy1c * WW;
        Da[i] = __ldg(row0 + ix0c);
        Db[i] = __ldg(row1 + ix0c);
        Dc[i] = __ldg(row0 + ix1c);
        Dd[i] = __ldg(row1 + ix1c);
    }

    // ---- phase C: weights + combine + store ----
    #pragma unroll
    for (int i = 0; i < 4; i++) {
        const float u2 = u2a[i];
        const float v2 = v2a[i];
        const int ix0 = __float2int_rd(u2);
        const int iy0 = __float2int_rd(v2);
        const int ix1c = min(max(ix0 + 1, 0), WW - 1);
        const int ix0c = min(max(ix0, 0), WW - 1);
        const int iy1c = min(max(iy0 + 1, 0), HH - 1);
        const int iy0c = min(max(iy0, 0), HH - 1);

        const float x0f = (float)ix0c, x1f = (float)ix1c;
        const float y0f = (float)iy0c, y1f = (float)iy1c;

        const float wa = (x1f - u2) * (y1f - v2);
        const float wb = (x1f - u2) * (v2 - y0f);
        const float wc = (u2 - x0f) * (y1f - v2);
        const float wd = (u2 - x0f) * (v2 - y0f);

        // d1_calc at each corner: w2z + d2 * (q20*ix + q21*iy + q22)
        const float rp0 = fmaf(q21, y0f, q22);
        const float rp1 = fmaf(q21, y1f, q22);
        const float px0 = q20 * x0f;
        const float px1 = q20 * x1f;

        const float Ia = fmaf(Da[i], px0 + rp0, w2z);
        const float Ib = fmaf(Db[i], px0 + rp1, w2z);
        const float Ic = fmaf(Dc[i], px1 + rp0, w2z);
        const float Id = fmaf(Dd[i], px1 + rp1, w2z);

        out[base + 32 * i] = wa * Ia + wb * Ib + wc * Ic + wd * Id;
    }
}

extern "C" void kernel_launch(void* const* d_in, const int* in_sizes, int n_in,
                              void* d_out, int out_size) {
    const float* d1   = (const float*)d_in[0];
    const float* d2   = (const float*)d_in[1];
    const float* tr   = (const float*)d_in[2];
    const float* rot  = (const float*)d_in[3];
    const float* intr = (const float*)d_in[4];
    float* out = (float*)d_out;

    const int blocks = (WW / TX) * (HH / TY) * BB;     // 10*128*16 = 20480
    depth_warp_kernel<<<blocks, 256>>>(d1, d2, tr, rot, intr, out);
}